// round 14
// baseline (speedup 1.0000x reference)
#include <cuda_runtime.h>
#include <cuda_fp16.h>
#include <math.h>
#include <stdint.h>

// ---------------------------------------------------------------------------
// MoE block via mma.sync fp16 (fp32 accum), ldmatrix(.trans), 3-stage
// cp.async pipeline (single-barrier mainloop), fused scatter epilogue,
// forked-stream prep overlap, FUSED GEMM1+GEMM2 with per-row-block
// device-side dependency (stream-K style backfill).
// tcgen05 unavailable (toolchain targets sm_103).
// ---------------------------------------------------------------------------

#define NEXP 8
#define DM 768
#define MLPD 3072
#define CAP_DET 256
#define CAP_CLS 32
#define RPE 2304
#define MTOT (NEXP * RPE)
#define NTOK_DET 8192
#define NTOK_CLS 1024
#define NTOK (NTOK_DET + NTOK_CLS)

#define CHUNK 64
#define ASTR 72
#define BSTR 136
#define A_HALVES (128 * ASTR)
#define B_HALVES (CHUNK * BSTR)
#define STAGE_HALVES (A_HALVES + B_HALVES)
#define NBUF 3
#define SMEM_DYN (NBUF * STAGE_HALVES * 2)   // 107520 bytes

#define G1_BX 24                              // MLPD/128
#define G1_BY 144                             // MTOT/128
#define G1_BLOCKS (G1_BX * G1_BY)             // 3456
#define G2_BX 6                               // DM/128
#define G2_BLOCKS (G2_BX * G1_BY)             // 864

// --------------------------- scratch ---------------------------------------
__device__ __half g_xg[(size_t)MTOT * DM];
__device__ __half g_h [(size_t)MTOT * MLPD];
__device__ __half g_w1h[(size_t)NEXP * DM * MLPD];   // [E, K=768,  N=3072]
__device__ __half g_w2h[(size_t)NEXP * MLPD * DM];   // [E, K=3072, N=768]
__device__ float  g_wrt[2][NEXP * DM];
__device__ int    g_row_src[MTOT];
__device__ float  g_row_gate[MTOT];
__device__ signed char g_tok_e[NTOK][2];
__device__ float  g_tok_p[NTOK][2];
__device__ int    g_sync[G1_BY];              // per-row-block completion count

// --------------------------- helpers ---------------------------------------
__device__ __forceinline__ uint32_t smem_u32(const void* p) {
    uint32_t a;
    asm("{ .reg .u64 t; cvta.to.shared.u64 t, %1; cvt.u32.u64 %0, t; }"
        : "=r"(a) : "l"(p));
    return a;
}
__device__ __forceinline__ void cp_async16(uint32_t sdst, const void* gsrc) {
    asm volatile("cp.async.cg.shared.global [%0], [%1], 16;"
                 :: "r"(sdst), "l"(gsrc) : "memory");
}
__device__ __forceinline__ void cp_commit() {
    asm volatile("cp.async.commit_group;" ::: "memory");
}
template<int N>
__device__ __forceinline__ void cp_wait() {
    asm volatile("cp.async.wait_group %0;" :: "n"(N) : "memory");
}
__device__ __forceinline__ void ldsm_x4(uint32_t* r, uint32_t addr) {
    asm volatile("ldmatrix.sync.aligned.m8n8.x4.shared.b16 {%0,%1,%2,%3}, [%4];"
                 : "=r"(r[0]), "=r"(r[1]), "=r"(r[2]), "=r"(r[3]) : "r"(addr));
}
__device__ __forceinline__ void ldsm_x4_trans(uint32_t* r, uint32_t addr) {
    asm volatile("ldmatrix.sync.aligned.m8n8.x4.trans.shared.b16 {%0,%1,%2,%3}, [%4];"
                 : "=r"(r[0]), "=r"(r[1]), "=r"(r[2]), "=r"(r[3]) : "r"(addr));
}
__device__ __forceinline__ void mma_f16(float* d, const uint32_t* a,
                                        const uint32_t* b) {
    asm volatile(
        "mma.sync.aligned.m16n8k16.row.col.f32.f16.f16.f32 "
        "{%0,%1,%2,%3}, {%4,%5,%6,%7}, {%8,%9}, {%0,%1,%2,%3};"
        : "+f"(d[0]), "+f"(d[1]), "+f"(d[2]), "+f"(d[3])
        : "r"(a[0]), "r"(a[1]), "r"(a[2]), "r"(a[3]),
          "r"(b[0]), "r"(b[1]));
}
__device__ __forceinline__ float gelu_tanh(float x) {
    float x3 = x * x * x;
    return 0.5f * x * (1.0f + tanhf(0.7978845608028654f * (x + 0.044715f * x3)));
}

// --------------------- branch s2: weight converts + zero --------------------
#define W4_COUNT   (NEXP * DM * MLPD / 4)
#define OUT4_COUNT (NTOK * DM / 4)

__global__ void convw1_kernel(const float* __restrict__ w1) {
    long long stride = (long long)gridDim.x * blockDim.x;
    for (long long j = blockIdx.x * (long long)blockDim.x + threadIdx.x;
         j < W4_COUNT; j += stride) {
        float4 v = ((const float4*)w1)[j];
        __half2* d = (__half2*)g_w1h + j * 2;
        d[0] = __floats2half2_rn(v.x, v.y);
        d[1] = __floats2half2_rn(v.z, v.w);
    }
}

__global__ void convw2z_kernel(const float* __restrict__ w2,
                               float* __restrict__ out) {
    long long stride = (long long)gridDim.x * blockDim.x;
    const long long total = W4_COUNT + OUT4_COUNT;
    for (long long i = blockIdx.x * (long long)blockDim.x + threadIdx.x;
         i < total; i += stride) {
        if (i < W4_COUNT) {
            float4 v = ((const float4*)w2)[i];
            __half2* d = (__half2*)g_w2h + i * 2;
            d[0] = __floats2half2_rn(v.x, v.y);
            d[1] = __floats2half2_rn(v.z, v.w);
        } else {
            ((float4*)out)[i - W4_COUNT] = make_float4(0.f, 0.f, 0.f, 0.f);
        }
    }
}

// ------------- router weight transpose [D,E] -> [E,D] + sync reset ----------
__global__ void wrt_kernel(const float* __restrict__ wr0,
                           const float* __restrict__ wr1) {
    int i = blockIdx.x * blockDim.x + threadIdx.x;
    if (i < G1_BY) g_sync[i] = 0;
    if (i >= DM * NEXP) return;
    int d = i / NEXP, e = i % NEXP;
    g_wrt[0][e * DM + d] = wr0[i];
    g_wrt[1][e * DM + d] = wr1[i];
}

// --------------------------- router (merged, smem weights) -------------------
// Also initializes g_row_src (16 ints per block; 1152 blocks * 16 = MTOT).
__global__ __launch_bounds__(256)
void router_kernel(const float* __restrict__ xdet,
                   const float* __restrict__ xcls) {
    __shared__ float sw[NEXP * DM];
    int b = blockIdx.x;
    int tid = threadIdx.x;
    if (tid < 16) g_row_src[b * 16 + tid] = -1;
    int which = (b < NTOK_DET / 8) ? 0 : 1;
    const float4* wsrc = (const float4*)g_wrt[which];
#pragma unroll
    for (int j = 0; j < 6; j++)
        ((float4*)sw)[j * 256 + tid] = wsrc[j * 256 + tid];
    __syncthreads();

    int wid = tid >> 5, lane = tid & 31;
    int t = b * 8 + wid;
    const float* xp = (t < NTOK_DET)
        ? (xdet + (size_t)t * DM)
        : (xcls + (size_t)(t - NTOK_DET) * DM);
    const float4* xr = (const float4*)xp;

    float acc[NEXP];
#pragma unroll
    for (int e = 0; e < NEXP; e++) acc[e] = 0.f;
#pragma unroll
    for (int it = 0; it < 6; it++) {
        int d4 = it * 32 + lane;
        float4 xv = xr[d4];
#pragma unroll
        for (int e = 0; e < NEXP; e++) {
            float4 wv = ((const float4*)(sw + e * DM))[d4];
            acc[e] += xv.x * wv.x + xv.y * wv.y + xv.z * wv.z + xv.w * wv.w;
        }
    }
#pragma unroll
    for (int e = 0; e < NEXP; e++) {
#pragma unroll
        for (int off = 16; off > 0; off >>= 1)
            acc[e] += __shfl_xor_sync(0xffffffffu, acc[e], off);
    }
    if (lane == 0) {
        float mx = acc[0];
#pragma unroll
        for (int e = 1; e < NEXP; e++) mx = fmaxf(mx, acc[e]);
        float p[NEXP]; float s = 0.f;
#pragma unroll
        for (int e = 0; e < NEXP; e++) { p[e] = expf(acc[e] - mx); s += p[e]; }
        float inv = 1.0f / s;
        int e0 = 0;
#pragma unroll
        for (int e = 1; e < NEXP; e++) if (p[e] > p[e0]) e0 = e;
        int e1 = (e0 == 0) ? 1 : 0;
#pragma unroll
        for (int e = 0; e < NEXP; e++) if (e != e0 && p[e] > p[e1]) e1 = e;
        g_tok_e[t][0] = (signed char)e0;
        g_tok_e[t][1] = (signed char)e1;
        g_tok_p[t][0] = p[e0] * inv;
        g_tok_p[t][1] = p[e1] * inv;
    }
}

// ------------------ positions (merged det+cls, grid 16) ----------------------
__global__ void positions_kernel() {
    __shared__ signed char se0[1024], se1[1024];
    __shared__ float sg0[1024], sg1[1024];
    int blk = blockIdx.x;
    int det = (blk < 8);
    int g = det ? blk : blk - 8;
    int S = det ? 1024 : 128;
    int C = det ? CAP_DET : CAP_CLS;
    int tok_base = det ? 0 : NTOK_DET;
    int row_off = det ? 0 : 2048;
    int tid = threadIdx.x;
    for (int t = tid; t < S; t += blockDim.x) {
        int gt = tok_base + g * S + t;
        se0[t] = g_tok_e[gt][0];
        se1[t] = g_tok_e[gt][1];
        sg0[t] = g_tok_p[gt][0];
        sg1[t] = g_tok_p[gt][1];
    }
    __syncthreads();
    int e = tid >> 5;
    int lane = tid & 31;
    int base = 0;
    int total = 2 * S;
    for (int j0 = 0; j0 < total; j0 += 32) {
        int j = j0 + lane;
        int exp_j = -1;
        if (j < total) exp_j = (j < S) ? (int)se0[j] : (int)se1[j - S];
        bool m = (exp_j == e);
        unsigned mask = __ballot_sync(0xffffffffu, m);
        if (m) {
            int pos = base + __popc(mask & ((1u << lane) - 1u));
            if (pos < C) {
                int t = (j < S) ? j : (j - S);
                int gt = tok_base + g * S + t;
                float gate = (j < S) ? sg0[t] : sg1[t];
                int row = e * RPE + row_off + g * C + pos;
                g_row_src[row] = gt;
                g_row_gate[row] = gate;
            }
        }
        base += __popc(mask);
    }
}

// --------------------------- gather (fp32 -> half) ---------------------------
__global__ void gather_kernel(const float* __restrict__ xdet,
                              const float* __restrict__ xcls) {
    int row = blockIdx.x;
    int i = threadIdx.x;
    int src = g_row_src[row];
    uint2 packed = make_uint2(0u, 0u);
    if (src >= 0) {
        const float* xp = (src < NTOK_DET)
            ? (xdet + (size_t)src * DM)
            : (xcls + (size_t)(src - NTOK_DET) * DM);
        float4 v = ((const float4*)xp)[i];
        __half2 h0 = __floats2half2_rn(v.x, v.y);
        __half2 h1 = __floats2half2_rn(v.z, v.w);
        packed.x = *(uint32_t*)&h0;
        packed.y = *(uint32_t*)&h1;
    }
    ((uint2*)(g_xg + (size_t)row * DM))[i] = packed;
}

// --------------------------- mma.sync fp16 GEMM ------------------------------
// FUSE=false: C[M,N] = gelu(A*W + b) stored half (GEMM1)
// FUSE=true : out[src(row)] += gate(row) * (A*W + b)   (GEMM2 + scatter)
template<int K, int NTOT, bool FUSE>
__device__ __forceinline__ void tc_gemm(int bx, int by,
                                        const __half* __restrict__ A,
                                        const __half* __restrict__ W,
                                        const float* __restrict__ bias,
                                        __half* __restrict__ C,
                                        float* __restrict__ out) {
    extern __shared__ __half smem[];
    int tid = threadIdx.x;
    int wid = tid >> 5, lane = tid & 31;
    int gid = lane >> 2, tig = lane & 3;
    int warp_m = wid & 1, warp_n = wid >> 1;
    int m_base = warp_m * 64, n_base = warp_n * 32;
    int e = (by * 128) / RPE;
    const __half* Ab = A + (size_t)by * 128 * K;
    const __half* Wb = W + (size_t)e * K * NTOT + (size_t)bx * 128;

    uint32_t a_off = (uint32_t)((m_base + (lane & 15)) * ASTR + ((lane >> 4) << 3));
    uint32_t b_off = (uint32_t)((((lane >> 3) & 1) * 8 + (lane & 7)) * BSTR
                                + n_base + ((lane >> 4) << 3));

    float acc[4][4][4];
#pragma unroll
    for (int mi = 0; mi < 4; mi++)
#pragma unroll
        for (int ni = 0; ni < 4; ni++)
#pragma unroll
            for (int q = 0; q < 4; q++) acc[mi][ni][q] = 0.f;

    const int NC = K / CHUNK;
    uint32_t sbase = smem_u32(smem);

    auto issue_stage = [&](int c) {
        int buf = c % NBUF;
        uint32_t as = sbase + (uint32_t)(buf * STAGE_HALVES) * 2u;
        uint32_t bs = as + (uint32_t)A_HALVES * 2u;
        int kc = c * CHUNK;
#pragma unroll
        for (int j = 0; j < 4; j++) {
            int idx = j * 256 + tid;
            int row = idx >> 3, seg = idx & 7;
            cp_async16(as + (uint32_t)(row * ASTR + seg * 8) * 2u,
                       Ab + (size_t)row * K + kc + seg * 8);
        }
#pragma unroll
        for (int j = 0; j < 4; j++) {
            int idx = j * 256 + tid;
            int row = idx >> 4, seg = idx & 15;
            cp_async16(bs + (uint32_t)(row * BSTR + seg * 8) * 2u,
                       Wb + (size_t)(kc + row) * NTOT + seg * 8);
        }
        cp_commit();
    };

    issue_stage(0);
    if (NC > 1) issue_stage(1);
    for (int c = 0; c < NC; c++) {
        if (c + 1 < NC) cp_wait<1>(); else cp_wait<0>();
        __syncthreads();                       // publishes chunk c; fences c-1 reads
        if (c + 2 < NC) issue_stage(c + 2);    // safe: all warps done with this buf

        uint32_t as = sbase + (uint32_t)((c % NBUF) * STAGE_HALVES) * 2u;
        uint32_t bs = as + (uint32_t)A_HALVES * 2u;
        uint32_t a_base = as + a_off * 2u;
        uint32_t b_base = bs + b_off * 2u;
#pragma unroll
        for (int kk = 0; kk < CHUNK; kk += 16) {
            uint32_t afr[4][4];
#pragma unroll
            for (int mi = 0; mi < 4; mi++)
                ldsm_x4(afr[mi], a_base + (uint32_t)(mi * 16 * ASTR + kk) * 2u);
            uint32_t bfr[2][4];
#pragma unroll
            for (int p = 0; p < 2; p++)
                ldsm_x4_trans(bfr[p], b_base + (uint32_t)(kk * BSTR + p * 16) * 2u);
#pragma unroll
            for (int mi = 0; mi < 4; mi++)
#pragma unroll
                for (int ni = 0; ni < 4; ni++)
                    mma_f16(acc[mi][ni], afr[mi], &bfr[ni >> 1][(ni & 1) * 2]);
        }
    }

    if (!FUSE) {
#pragma unroll
        for (int ni = 0; ni < 4; ni++) {
            int cb = bx * 128 + n_base + ni * 8 + 2 * tig;
            float b0 = bias[e * NTOT + cb];
            float b1 = bias[e * NTOT + cb + 1];
#pragma unroll
            for (int mi = 0; mi < 4; mi++) {
                int r0 = by * 128 + m_base + mi * 16 + gid;
                float v0 = gelu_tanh(acc[mi][ni][0] + b0);
                float v1 = gelu_tanh(acc[mi][ni][1] + b1);
                float v2 = gelu_tanh(acc[mi][ni][2] + b0);
                float v3 = gelu_tanh(acc[mi][ni][3] + b1);
                *(__half2*)(C + (size_t)r0 * NTOT + cb)       = __floats2half2_rn(v0, v1);
                *(__half2*)(C + (size_t)(r0 + 8) * NTOT + cb) = __floats2half2_rn(v2, v3);
            }
        }
    } else {
        int rsrc[8]; float rg[8];
#pragma unroll
        for (int mi = 0; mi < 4; mi++) {
            int r0 = by * 128 + m_base + mi * 16 + gid;
            rsrc[mi * 2]     = __ldg(&g_row_src[r0]);
            rsrc[mi * 2 + 1] = __ldg(&g_row_src[r0 + 8]);
            rg[mi * 2]     = rsrc[mi * 2]     >= 0 ? __ldg(&g_row_gate[r0])     : 0.f;
            rg[mi * 2 + 1] = rsrc[mi * 2 + 1] >= 0 ? __ldg(&g_row_gate[r0 + 8]) : 0.f;
        }
#pragma unroll
        for (int ni = 0; ni < 4; ni++) {
            int cb = bx * 128 + n_base + ni * 8 + 2 * tig;
            float b0 = bias[e * NTOT + cb];
            float b1 = bias[e * NTOT + cb + 1];
#pragma unroll
            for (int mi = 0; mi < 4; mi++) {
                int src0 = rsrc[mi * 2], src1 = rsrc[mi * 2 + 1];
                if (src0 >= 0) {
                    float g0 = rg[mi * 2];
                    atomicAdd(out + (size_t)src0 * DM + cb,     g0 * (acc[mi][ni][0] + b0));
                    atomicAdd(out + (size_t)src0 * DM + cb + 1, g0 * (acc[mi][ni][1] + b1));
                }
                if (src1 >= 0) {
                    float g1 = rg[mi * 2 + 1];
                    atomicAdd(out + (size_t)src1 * DM + cb,     g1 * (acc[mi][ni][2] + b0));
                    atomicAdd(out + (size_t)src1 * DM + cb + 1, g1 * (acc[mi][ni][3] + b1));
                }
            }
        }
    }
}

// ------------- fused GEMM1+GEMM2 with per-row-block dependency ---------------
__global__ __launch_bounds__(256, 2)
void gemm12_tc(const float* __restrict__ b1, const float* __restrict__ b2,
               float* __restrict__ out) {
    int bid = blockIdx.x;
    if (bid < G1_BLOCKS) {
        int bx = bid % G1_BX, by = bid / G1_BX;
        tc_gemm<DM, MLPD, false>(bx, by, g_xg, g_w1h, b1, g_h, nullptr);
        __threadfence();                       // publish h stores device-wide
        __syncthreads();                       // all threads' stores fenced
        if (threadIdx.x == 0) atomicAdd(&g_sync[by], 1);
    } else {
        int b = bid - G1_BLOCKS;
        int bx = b % G2_BX, by = b / G2_BX;
        if (threadIdx.x == 0) {
            while (*(volatile int*)&g_sync[by] < G1_BX) __nanosleep(64);
        }
        __syncthreads();
        __threadfence();                       // acquire: order h reads after flag
        tc_gemm<MLPD, DM, true>(bx, by, g_h, g_w2h, b2, nullptr, out);
    }
}

// --------------------------- launch -----------------------------------------
extern "C" void kernel_launch(void* const* d_in, const int* in_sizes, int n_in,
                              void* d_out, int out_size) {
    (void)in_sizes; (void)n_in; (void)out_size;
    const float* xdet = (const float*)d_in[0];
    const float* xcls = (const float*)d_in[1];
    const float* wrd  = (const float*)d_in[2];
    const float* wrc  = (const float*)d_in[3];
    const float* w1   = (const float*)d_in[4];
    const float* b1   = (const float*)d_in[5];
    const float* w2   = (const float*)d_in[6];
    const float* b2   = (const float*)d_in[7];
    float* out = (float*)d_out;

    static cudaStream_t s2 = nullptr;
    static cudaEvent_t ev0 = nullptr, ev2 = nullptr;
    if (!s2) {
        cudaStreamCreateWithFlags(&s2, cudaStreamNonBlocking);
        cudaEventCreateWithFlags(&ev0, cudaEventDisableTiming);
        cudaEventCreateWithFlags(&ev2, cudaEventDisableTiming);
        cudaFuncSetAttribute(gemm12_tc, cudaFuncAttributeMaxDynamicSharedMemorySize, SMEM_DYN);
    }

    // fork: weight conversion branch on s2
    cudaEventRecord(ev0, 0);
    cudaStreamWaitEvent(s2, ev0, 0);
    convw1_kernel<<<2048, 256, 0, s2>>>(w1);
    convw2z_kernel<<<2048, 256, 0, s2>>>(w2, out);
    cudaEventRecord(ev2, s2);

    // main branch: routing pipeline
    wrt_kernel<<<(DM * NEXP + 255) / 256, 256>>>(wrd, wrc);
    router_kernel<<<NTOK / 8, 256>>>(xdet, xcls);
    positions_kernel<<<16, 256>>>();
    gather_kernel<<<MTOT, 192>>>(xdet, xcls);

    // join and run fused GEMM1+GEMM2
    cudaStreamWaitEvent(0, ev2, 0);
    gemm12_tc<<<G1_BLOCKS + G2_BLOCKS, 256, SMEM_DYN>>>(b1, b2, out);
}

// round 15
// speedup vs baseline: 1.0136x; 1.0136x over previous
#include <cuda_runtime.h>
#include <cuda_fp16.h>
#include <math.h>
#include <stdint.h>

// ---------------------------------------------------------------------------
// MoE block via mma.sync fp16 (fp32 accum), ldmatrix(.trans), 3-stage
// cp.async pipeline (single-barrier mainloop), fused scatter epilogue,
// forked-stream prep overlap. GEMM2 uses a 128x256 tile (512 thr) to halve
// its L2 A-traffic. tcgen05 unavailable (toolchain targets sm_103).
// ---------------------------------------------------------------------------

#define NEXP 8
#define DM 768
#define MLPD 3072
#define CAP_DET 256
#define CAP_CLS 32
#define RPE 2304
#define MTOT (NEXP * RPE)
#define NTOK_DET 8192
#define NTOK_CLS 1024
#define NTOK (NTOK_DET + NTOK_CLS)

#define CHUNK 64
#define ASTR 72
#define BSTR 136
#define A_HALVES (128 * ASTR)
#define B_HALVES (CHUNK * BSTR)
#define STAGE_HALVES (A_HALVES + B_HALVES)
#define NBUF 3
#define SMEM_DYN (NBUF * STAGE_HALVES * 2)     // 107520 bytes (GEMM1)

#define BSTR2 264                               // GEMM2 B stride (256+8)
#define B2_HALVES (CHUNK * BSTR2)               // 16896
#define STAGE2_HALVES (A_HALVES + B2_HALVES)    // 26112
#define SMEM_DYN2 (NBUF * STAGE2_HALVES * 2)    // 156672 bytes (GEMM2)

// --------------------------- scratch ---------------------------------------
__device__ __half g_xg[(size_t)MTOT * DM];
__device__ __half g_h [(size_t)MTOT * MLPD];
__device__ __half g_w1h[(size_t)NEXP * DM * MLPD];   // [E, K=768,  N=3072]
__device__ __half g_w2h[(size_t)NEXP * MLPD * DM];   // [E, K=3072, N=768]
__device__ float  g_wrt[2][NEXP * DM];
__device__ int    g_row_src[MTOT];
__device__ float  g_row_gate[MTOT];
__device__ signed char g_tok_e[NTOK][2];
__device__ float  g_tok_p[NTOK][2];

// --------------------------- helpers ---------------------------------------
__device__ __forceinline__ uint32_t smem_u32(const void* p) {
    uint32_t a;
    asm("{ .reg .u64 t; cvta.to.shared.u64 t, %1; cvt.u32.u64 %0, t; }"
        : "=r"(a) : "l"(p));
    return a;
}
__device__ __forceinline__ void cp_async16(uint32_t sdst, const void* gsrc) {
    asm volatile("cp.async.cg.shared.global [%0], [%1], 16;"
                 :: "r"(sdst), "l"(gsrc) : "memory");
}
__device__ __forceinline__ void cp_commit() {
    asm volatile("cp.async.commit_group;" ::: "memory");
}
template<int N>
__device__ __forceinline__ void cp_wait() {
    asm volatile("cp.async.wait_group %0;" :: "n"(N) : "memory");
}
__device__ __forceinline__ void ldsm_x4(uint32_t* r, uint32_t addr) {
    asm volatile("ldmatrix.sync.aligned.m8n8.x4.shared.b16 {%0,%1,%2,%3}, [%4];"
                 : "=r"(r[0]), "=r"(r[1]), "=r"(r[2]), "=r"(r[3]) : "r"(addr));
}
__device__ __forceinline__ void ldsm_x4_trans(uint32_t* r, uint32_t addr) {
    asm volatile("ldmatrix.sync.aligned.m8n8.x4.trans.shared.b16 {%0,%1,%2,%3}, [%4];"
                 : "=r"(r[0]), "=r"(r[1]), "=r"(r[2]), "=r"(r[3]) : "r"(addr));
}
__device__ __forceinline__ void mma_f16(float* d, const uint32_t* a,
                                        const uint32_t* b) {
    asm volatile(
        "mma.sync.aligned.m16n8k16.row.col.f32.f16.f16.f32 "
        "{%0,%1,%2,%3}, {%4,%5,%6,%7}, {%8,%9}, {%0,%1,%2,%3};"
        : "+f"(d[0]), "+f"(d[1]), "+f"(d[2]), "+f"(d[3])
        : "r"(a[0]), "r"(a[1]), "r"(a[2]), "r"(a[3]),
          "r"(b[0]), "r"(b[1]));
}
__device__ __forceinline__ float gelu_tanh(float x) {
    float x3 = x * x * x;
    return 0.5f * x * (1.0f + tanhf(0.7978845608028654f * (x + 0.044715f * x3)));
}

// --------------------- branch s2: weight converts + zero --------------------
#define W4_COUNT   (NEXP * DM * MLPD / 4)
#define OUT4_COUNT (NTOK * DM / 4)

__global__ void convw1_kernel(const float* __restrict__ w1) {
    long long stride = (long long)gridDim.x * blockDim.x;
    for (long long j = blockIdx.x * (long long)blockDim.x + threadIdx.x;
         j < W4_COUNT; j += stride) {
        float4 v = ((const float4*)w1)[j];
        __half2* d = (__half2*)g_w1h + j * 2;
        d[0] = __floats2half2_rn(v.x, v.y);
        d[1] = __floats2half2_rn(v.z, v.w);
    }
}

__global__ void convw2z_kernel(const float* __restrict__ w2,
                               float* __restrict__ out) {
    long long stride = (long long)gridDim.x * blockDim.x;
    const long long total = W4_COUNT + OUT4_COUNT;
    for (long long i = blockIdx.x * (long long)blockDim.x + threadIdx.x;
         i < total; i += stride) {
        if (i < W4_COUNT) {
            float4 v = ((const float4*)w2)[i];
            __half2* d = (__half2*)g_w2h + i * 2;
            d[0] = __floats2half2_rn(v.x, v.y);
            d[1] = __floats2half2_rn(v.z, v.w);
        } else {
            ((float4*)out)[i - W4_COUNT] = make_float4(0.f, 0.f, 0.f, 0.f);
        }
    }
}

// -------------------- router weight transpose [D,E] -> [E,D] -----------------
__global__ void wrt_kernel(const float* __restrict__ wr0,
                           const float* __restrict__ wr1) {
    int i = blockIdx.x * blockDim.x + threadIdx.x;
    if (i >= DM * NEXP) return;
    int d = i / NEXP, e = i % NEXP;
    g_wrt[0][e * DM + d] = wr0[i];
    g_wrt[1][e * DM + d] = wr1[i];
}

// --------------------------- router (merged, smem weights) -------------------
__global__ __launch_bounds__(256)
void router_kernel(const float* __restrict__ xdet,
                   const float* __restrict__ xcls) {
    __shared__ float sw[NEXP * DM];
    int b = blockIdx.x;
    int tid = threadIdx.x;
    if (tid < 16) g_row_src[b * 16 + tid] = -1;
    int which = (b < NTOK_DET / 8) ? 0 : 1;
    const float4* wsrc = (const float4*)g_wrt[which];
#pragma unroll
    for (int j = 0; j < 6; j++)
        ((float4*)sw)[j * 256 + tid] = wsrc[j * 256 + tid];
    __syncthreads();

    int wid = tid >> 5, lane = tid & 31;
    int t = b * 8 + wid;
    const float* xp = (t < NTOK_DET)
        ? (xdet + (size_t)t * DM)
        : (xcls + (size_t)(t - NTOK_DET) * DM);
    const float4* xr = (const float4*)xp;

    float acc[NEXP];
#pragma unroll
    for (int e = 0; e < NEXP; e++) acc[e] = 0.f;
#pragma unroll
    for (int it = 0; it < 6; it++) {
        int d4 = it * 32 + lane;
        float4 xv = xr[d4];
#pragma unroll
        for (int e = 0; e < NEXP; e++) {
            float4 wv = ((const float4*)(sw + e * DM))[d4];
            acc[e] += xv.x * wv.x + xv.y * wv.y + xv.z * wv.z + xv.w * wv.w;
        }
    }
#pragma unroll
    for (int e = 0; e < NEXP; e++) {
#pragma unroll
        for (int off = 16; off > 0; off >>= 1)
            acc[e] += __shfl_xor_sync(0xffffffffu, acc[e], off);
    }
    if (lane == 0) {
        float mx = acc[0];
#pragma unroll
        for (int e = 1; e < NEXP; e++) mx = fmaxf(mx, acc[e]);
        float p[NEXP]; float s = 0.f;
#pragma unroll
        for (int e = 0; e < NEXP; e++) { p[e] = expf(acc[e] - mx); s += p[e]; }
        float inv = 1.0f / s;
        int e0 = 0;
#pragma unroll
        for (int e = 1; e < NEXP; e++) if (p[e] > p[e0]) e0 = e;
        int e1 = (e0 == 0) ? 1 : 0;
#pragma unroll
        for (int e = 0; e < NEXP; e++) if (e != e0 && p[e] > p[e1]) e1 = e;
        g_tok_e[t][0] = (signed char)e0;
        g_tok_e[t][1] = (signed char)e1;
        g_tok_p[t][0] = p[e0] * inv;
        g_tok_p[t][1] = p[e1] * inv;
    }
}

// ------------------ positions (merged det+cls, grid 16) ----------------------
__global__ void positions_kernel() {
    __shared__ signed char se0[1024], se1[1024];
    __shared__ float sg0[1024], sg1[1024];
    int blk = blockIdx.x;
    int det = (blk < 8);
    int g = det ? blk : blk - 8;
    int S = det ? 1024 : 128;
    int C = det ? CAP_DET : CAP_CLS;
    int tok_base = det ? 0 : NTOK_DET;
    int row_off = det ? 0 : 2048;
    int tid = threadIdx.x;
    for (int t = tid; t < S; t += blockDim.x) {
        int gt = tok_base + g * S + t;
        se0[t] = g_tok_e[gt][0];
        se1[t] = g_tok_e[gt][1];
        sg0[t] = g_tok_p[gt][0];
        sg1[t] = g_tok_p[gt][1];
    }
    __syncthreads();
    int e = tid >> 5;
    int lane = tid & 31;
    int base = 0;
    int total = 2 * S;
    for (int j0 = 0; j0 < total; j0 += 32) {
        int j = j0 + lane;
        int exp_j = -1;
        if (j < total) exp_j = (j < S) ? (int)se0[j] : (int)se1[j - S];
        bool m = (exp_j == e);
        unsigned mask = __ballot_sync(0xffffffffu, m);
        if (m) {
            int pos = base + __popc(mask & ((1u << lane) - 1u));
            if (pos < C) {
                int t = (j < S) ? j : (j - S);
                int gt = tok_base + g * S + t;
                float gate = (j < S) ? sg0[t] : sg1[t];
                int row = e * RPE + row_off + g * C + pos;
                g_row_src[row] = gt;
                g_row_gate[row] = gate;
            }
        }
        base += __popc(mask);
    }
}

// --------------------------- gather (fp32 -> half) ---------------------------
__global__ void gather_kernel(const float* __restrict__ xdet,
                              const float* __restrict__ xcls) {
    int row = blockIdx.x;
    int i = threadIdx.x;
    int src = g_row_src[row];
    uint2 packed = make_uint2(0u, 0u);
    if (src >= 0) {
        const float* xp = (src < NTOK_DET)
            ? (xdet + (size_t)src * DM)
            : (xcls + (size_t)(src - NTOK_DET) * DM);
        float4 v = ((const float4*)xp)[i];
        __half2 h0 = __floats2half2_rn(v.x, v.y);
        __half2 h1 = __floats2half2_rn(v.z, v.w);
        packed.x = *(uint32_t*)&h0;
        packed.y = *(uint32_t*)&h1;
    }
    ((uint2*)(g_xg + (size_t)row * DM))[i] = packed;
}

// --------------------- GEMM1: 128x128 tile, 256 threads ----------------------
// C[M,N] = gelu(A*W1 + b1) stored half.
__global__ __launch_bounds__(256, 2)
void gemm1_tc(const float* __restrict__ bias) {
    extern __shared__ __half smem[];
    const int K = DM, NTOT = MLPD;
    int tid = threadIdx.x;
    int wid = tid >> 5, lane = tid & 31;
    int gid = lane >> 2, tig = lane & 3;
    int warp_m = wid & 1, warp_n = wid >> 1;
    int m_base = warp_m * 64, n_base = warp_n * 32;
    int bx = blockIdx.x, by = blockIdx.y;
    int e = (by * 128) / RPE;
    const __half* Ab = g_xg + (size_t)by * 128 * K;
    const __half* Wb = g_w1h + (size_t)e * K * NTOT + (size_t)bx * 128;

    uint32_t a_off = (uint32_t)((m_base + (lane & 15)) * ASTR + ((lane >> 4) << 3));
    uint32_t b_off = (uint32_t)((((lane >> 3) & 1) * 8 + (lane & 7)) * BSTR
                                + n_base + ((lane >> 4) << 3));

    float acc[4][4][4];
#pragma unroll
    for (int mi = 0; mi < 4; mi++)
#pragma unroll
        for (int ni = 0; ni < 4; ni++)
#pragma unroll
            for (int q = 0; q < 4; q++) acc[mi][ni][q] = 0.f;

    const int NC = K / CHUNK;
    uint32_t sbase = smem_u32(smem);

    auto issue_stage = [&](int c) {
        int buf = c % NBUF;
        uint32_t as = sbase + (uint32_t)(buf * STAGE_HALVES) * 2u;
        uint32_t bs = as + (uint32_t)A_HALVES * 2u;
        int kc = c * CHUNK;
#pragma unroll
        for (int j = 0; j < 4; j++) {
            int idx = j * 256 + tid;
            int row = idx >> 3, seg = idx & 7;
            cp_async16(as + (uint32_t)(row * ASTR + seg * 8) * 2u,
                       Ab + (size_t)row * K + kc + seg * 8);
        }
#pragma unroll
        for (int j = 0; j < 4; j++) {
            int idx = j * 256 + tid;
            int row = idx >> 4, seg = idx & 15;
            cp_async16(bs + (uint32_t)(row * BSTR + seg * 8) * 2u,
                       Wb + (size_t)(kc + row) * NTOT + seg * 8);
        }
        cp_commit();
    };

    issue_stage(0);
    issue_stage(1);
    for (int c = 0; c < NC; c++) {
        if (c + 1 < NC) cp_wait<1>(); else cp_wait<0>();
        __syncthreads();
        if (c + 2 < NC) issue_stage(c + 2);

        uint32_t as = sbase + (uint32_t)((c % NBUF) * STAGE_HALVES) * 2u;
        uint32_t bs = as + (uint32_t)A_HALVES * 2u;
        uint32_t a_base = as + a_off * 2u;
        uint32_t b_base = bs + b_off * 2u;
#pragma unroll
        for (int kk = 0; kk < CHUNK; kk += 16) {
            uint32_t afr[4][4];
#pragma unroll
            for (int mi = 0; mi < 4; mi++)
                ldsm_x4(afr[mi], a_base + (uint32_t)(mi * 16 * ASTR + kk) * 2u);
            uint32_t bfr[2][4];
#pragma unroll
            for (int p = 0; p < 2; p++)
                ldsm_x4_trans(bfr[p], b_base + (uint32_t)(kk * BSTR + p * 16) * 2u);
#pragma unroll
            for (int mi = 0; mi < 4; mi++)
#pragma unroll
                for (int ni = 0; ni < 4; ni++)
                    mma_f16(acc[mi][ni], afr[mi], &bfr[ni >> 1][(ni & 1) * 2]);
        }
    }

#pragma unroll
    for (int ni = 0; ni < 4; ni++) {
        int cb = bx * 128 + n_base + ni * 8 + 2 * tig;
        float b0 = bias[e * NTOT + cb];
        float b1 = bias[e * NTOT + cb + 1];
#pragma unroll
        for (int mi = 0; mi < 4; mi++) {
            int r0 = by * 128 + m_base + mi * 16 + gid;
            float v0 = gelu_tanh(acc[mi][ni][0] + b0);
            float v1 = gelu_tanh(acc[mi][ni][1] + b1);
            float v2 = gelu_tanh(acc[mi][ni][2] + b0);
            float v3 = gelu_tanh(acc[mi][ni][3] + b1);
            *(__half2*)(g_h + (size_t)r0 * NTOT + cb)       = __floats2half2_rn(v0, v1);
            *(__half2*)(g_h + (size_t)(r0 + 8) * NTOT + cb) = __floats2half2_rn(v2, v3);
        }
    }
}

// ------------- GEMM2: 128x256 tile, 512 threads, fused scatter ---------------
// out[src(row)] += gate(row) * (h*W2 + b2). Same per-warp 64x32 tile code;
// 2 M-warps x 8 N-warps. Halves h re-reads through L2 (3 bx tiles vs 6).
__global__ __launch_bounds__(512, 1)
void gemm2_tc(const float* __restrict__ bias, float* __restrict__ out) {
    extern __shared__ __half smem[];
    const int K = MLPD, NTOT = DM;
    int tid = threadIdx.x;
    int wid = tid >> 5, lane = tid & 31;
    int gid = lane >> 2, tig = lane & 3;
    int warp_m = wid & 1, warp_n = wid >> 1;           // 0..1 x 0..7
    int m_base = warp_m * 64, n_base = warp_n * 32;
    int bx = blockIdx.x, by = blockIdx.y;
    int e = (by * 128) / RPE;
    const __half* Ab = g_h + (size_t)by * 128 * K;
    const __half* Wb = g_w2h + (size_t)e * K * NTOT + (size_t)bx * 256;

    uint32_t a_off = (uint32_t)((m_base + (lane & 15)) * ASTR + ((lane >> 4) << 3));
    uint32_t b_off = (uint32_t)((((lane >> 3) & 1) * 8 + (lane & 7)) * BSTR2
                                + n_base + ((lane >> 4) << 3));

    float acc[4][4][4];
#pragma unroll
    for (int mi = 0; mi < 4; mi++)
#pragma unroll
        for (int ni = 0; ni < 4; ni++)
#pragma unroll
            for (int q = 0; q < 4; q++) acc[mi][ni][q] = 0.f;

    const int NC = K / CHUNK;                          // 48
    uint32_t sbase = smem_u32(smem);

    auto issue_stage = [&](int c) {
        int buf = c % NBUF;
        uint32_t as = sbase + (uint32_t)(buf * STAGE2_HALVES) * 2u;
        uint32_t bs = as + (uint32_t)A_HALVES * 2u;
        int kc = c * CHUNK;
        // A: 128 rows x 64 halves = 1024 x 16B over 512 threads
#pragma unroll
        for (int j = 0; j < 2; j++) {
            int idx = j * 512 + tid;
            int row = idx >> 3, seg = idx & 7;
            cp_async16(as + (uint32_t)(row * ASTR + seg * 8) * 2u,
                       Ab + (size_t)row * K + kc + seg * 8);
        }
        // B: 64 k-rows x 256 n-halves = 2048 x 16B
#pragma unroll
        for (int j = 0; j < 4; j++) {
            int idx = j * 512 + tid;
            int row = idx >> 5, seg = idx & 31;
            cp_async16(bs + (uint32_t)(row * BSTR2 + seg * 8) * 2u,
                       Wb + (size_t)(kc + row) * NTOT + seg * 8);
        }
        cp_commit();
    };

    issue_stage(0);
    issue_stage(1);
    for (int c = 0; c < NC; c++) {
        if (c + 1 < NC) cp_wait<1>(); else cp_wait<0>();
        __syncthreads();
        if (c + 2 < NC) issue_stage(c + 2);

        uint32_t as = sbase + (uint32_t)((c % NBUF) * STAGE2_HALVES) * 2u;
        uint32_t bs = as + (uint32_t)A_HALVES * 2u;
        uint32_t a_base = as + a_off * 2u;
        uint32_t b_base = bs + b_off * 2u;
#pragma unroll
        for (int kk = 0; kk < CHUNK; kk += 16) {
            uint32_t afr[4][4];
#pragma unroll
            for (int mi = 0; mi < 4; mi++)
                ldsm_x4(afr[mi], a_base + (uint32_t)(mi * 16 * ASTR + kk) * 2u);
            uint32_t bfr[2][4];
#pragma unroll
            for (int p = 0; p < 2; p++)
                ldsm_x4_trans(bfr[p], b_base + (uint32_t)(kk * BSTR2 + p * 16) * 2u);
#pragma unroll
            for (int mi = 0; mi < 4; mi++)
#pragma unroll
                for (int ni = 0; ni < 4; ni++)
                    mma_f16(acc[mi][ni], afr[mi], &bfr[ni >> 1][(ni & 1) * 2]);
        }
    }

    // fused scatter epilogue: out[src] += gate * (acc + bias)
    int rsrc[8]; float rg[8];
#pragma unroll
    for (int mi = 0; mi < 4; mi++) {
        int r0 = by * 128 + m_base + mi * 16 + gid;
        rsrc[mi * 2]     = __ldg(&g_row_src[r0]);
        rsrc[mi * 2 + 1] = __ldg(&g_row_src[r0 + 8]);
        rg[mi * 2]     = rsrc[mi * 2]     >= 0 ? __ldg(&g_row_gate[r0])     : 0.f;
        rg[mi * 2 + 1] = rsrc[mi * 2 + 1] >= 0 ? __ldg(&g_row_gate[r0 + 8]) : 0.f;
    }
#pragma unroll
    for (int ni = 0; ni < 4; ni++) {
        int cb = bx * 256 + n_base + ni * 8 + 2 * tig;
        float b0 = bias[e * NTOT + cb];
        float b1 = bias[e * NTOT + cb + 1];
#pragma unroll
        for (int mi = 0; mi < 4; mi++) {
            int src0 = rsrc[mi * 2], src1 = rsrc[mi * 2 + 1];
            if (src0 >= 0) {
                float g0 = rg[mi * 2];
                atomicAdd(out + (size_t)src0 * DM + cb,     g0 * (acc[mi][ni][0] + b0));
                atomicAdd(out + (size_t)src0 * DM + cb + 1, g0 * (acc[mi][ni][1] + b1));
            }
            if (src1 >= 0) {
                float g1 = rg[mi * 2 + 1];
                atomicAdd(out + (size_t)src1 * DM + cb,     g1 * (acc[mi][ni][2] + b0));
                atomicAdd(out + (size_t)src1 * DM + cb + 1, g1 * (acc[mi][ni][3] + b1));
            }
        }
    }
}

// --------------------------- launch -----------------------------------------
extern "C" void kernel_launch(void* const* d_in, const int* in_sizes, int n_in,
                              void* d_out, int out_size) {
    (void)in_sizes; (void)n_in; (void)out_size;
    const float* xdet = (const float*)d_in[0];
    const float* xcls = (const float*)d_in[1];
    const float* wrd  = (const float*)d_in[2];
    const float* wrc  = (const float*)d_in[3];
    const float* w1   = (const float*)d_in[4];
    const float* b1   = (const float*)d_in[5];
    const float* w2   = (const float*)d_in[6];
    const float* b2   = (const float*)d_in[7];
    float* out = (float*)d_out;

    static cudaStream_t s2 = nullptr;
    static cudaEvent_t ev0 = nullptr, ev1 = nullptr, ev2 = nullptr;
    if (!s2) {
        cudaStreamCreateWithFlags(&s2, cudaStreamNonBlocking);
        cudaEventCreateWithFlags(&ev0, cudaEventDisableTiming);
        cudaEventCreateWithFlags(&ev1, cudaEventDisableTiming);
        cudaEventCreateWithFlags(&ev2, cudaEventDisableTiming);
        cudaFuncSetAttribute(gemm1_tc, cudaFuncAttributeMaxDynamicSharedMemorySize, SMEM_DYN);
        cudaFuncSetAttribute(gemm2_tc, cudaFuncAttributeMaxDynamicSharedMemorySize, SMEM_DYN2);
    }

    // fork: weight conversion branch on s2
    cudaEventRecord(ev0, 0);
    cudaStreamWaitEvent(s2, ev0, 0);
    convw1_kernel<<<2048, 256, 0, s2>>>(w1);
    cudaEventRecord(ev1, s2);
    convw2z_kernel<<<2048, 256, 0, s2>>>(w2, out);
    cudaEventRecord(ev2, s2);

    // main branch: routing pipeline
    wrt_kernel<<<(DM * NEXP + 255) / 256, 256>>>(wrd, wrc);
    router_kernel<<<NTOK / 8, 256>>>(xdet, xcls);
    positions_kernel<<<16, 256>>>();
    gather_kernel<<<MTOT, 192>>>(xdet, xcls);

    // join and run GEMMs
    cudaStreamWaitEvent(0, ev1, 0);
    gemm1_tc<<<dim3(MLPD / 128, MTOT / 128), 256, SMEM_DYN>>>(b1);
    cudaStreamWaitEvent(0, ev2, 0);
    gemm2_tc<<<dim3(DM / 256, MTOT / 128), 512, SMEM_DYN2>>>(b2, out);
}

// round 16
// speedup vs baseline: 1.0652x; 1.0510x over previous
#include <cuda_runtime.h>
#include <cuda_fp16.h>
#include <math.h>
#include <stdint.h>

// ---------------------------------------------------------------------------
// MoE block via mma.sync fp16 (fp32 accum), ldmatrix(.trans), 3-stage
// cp.async pipeline (single-barrier mainloop), fused scatter epilogue with
// vectorized red.global.add.v2.f32, forked-stream prep overlap.
// tcgen05 unavailable (toolchain targets sm_103).
// ---------------------------------------------------------------------------

#define NEXP 8
#define DM 768
#define MLPD 3072
#define CAP_DET 256
#define CAP_CLS 32
#define RPE 2304
#define MTOT (NEXP * RPE)
#define NTOK_DET 8192
#define NTOK_CLS 1024
#define NTOK (NTOK_DET + NTOK_CLS)

#define CHUNK 64
#define ASTR 72
#define BSTR 136
#define A_HALVES (128 * ASTR)
#define B_HALVES (CHUNK * BSTR)
#define STAGE_HALVES (A_HALVES + B_HALVES)
#define NBUF 3
#define SMEM_DYN (NBUF * STAGE_HALVES * 2)   // 107520 bytes

// --------------------------- scratch ---------------------------------------
__device__ __half g_xg[(size_t)MTOT * DM];
__device__ __half g_h [(size_t)MTOT * MLPD];
__device__ __half g_w1h[(size_t)NEXP * DM * MLPD];   // [E, K=768,  N=3072]
__device__ __half g_w2h[(size_t)NEXP * MLPD * DM];   // [E, K=3072, N=768]
__device__ float  g_wrt[2][NEXP * DM];
__device__ int    g_row_src[MTOT];
__device__ float  g_row_gate[MTOT];
__device__ signed char g_tok_e[NTOK][2];
__device__ float  g_tok_p[NTOK][2];

// --------------------------- helpers ---------------------------------------
__device__ __forceinline__ uint32_t smem_u32(const void* p) {
    uint32_t a;
    asm("{ .reg .u64 t; cvta.to.shared.u64 t, %1; cvt.u32.u64 %0, t; }"
        : "=r"(a) : "l"(p));
    return a;
}
__device__ __forceinline__ void cp_async16(uint32_t sdst, const void* gsrc) {
    asm volatile("cp.async.cg.shared.global [%0], [%1], 16;"
                 :: "r"(sdst), "l"(gsrc) : "memory");
}
__device__ __forceinline__ void cp_commit() {
    asm volatile("cp.async.commit_group;" ::: "memory");
}
template<int N>
__device__ __forceinline__ void cp_wait() {
    asm volatile("cp.async.wait_group %0;" :: "n"(N) : "memory");
}
__device__ __forceinline__ void ldsm_x4(uint32_t* r, uint32_t addr) {
    asm volatile("ldmatrix.sync.aligned.m8n8.x4.shared.b16 {%0,%1,%2,%3}, [%4];"
                 : "=r"(r[0]), "=r"(r[1]), "=r"(r[2]), "=r"(r[3]) : "r"(addr));
}
__device__ __forceinline__ void ldsm_x4_trans(uint32_t* r, uint32_t addr) {
    asm volatile("ldmatrix.sync.aligned.m8n8.x4.trans.shared.b16 {%0,%1,%2,%3}, [%4];"
                 : "=r"(r[0]), "=r"(r[1]), "=r"(r[2]), "=r"(r[3]) : "r"(addr));
}
__device__ __forceinline__ void mma_f16(float* d, const uint32_t* a,
                                        const uint32_t* b) {
    asm volatile(
        "mma.sync.aligned.m16n8k16.row.col.f32.f16.f16.f32 "
        "{%0,%1,%2,%3}, {%4,%5,%6,%7}, {%8,%9}, {%0,%1,%2,%3};"
        : "+f"(d[0]), "+f"(d[1]), "+f"(d[2]), "+f"(d[3])
        : "r"(a[0]), "r"(a[1]), "r"(a[2]), "r"(a[3]),
          "r"(b[0]), "r"(b[1]));
}
// vectorized global reduction: out[0] += a, out[1] += b (8B-aligned addr)
__device__ __forceinline__ void red_add_v2(float* addr, float a, float b) {
    asm volatile("red.global.add.v2.f32 [%0], {%1, %2};"
                 :: "l"(addr), "f"(a), "f"(b) : "memory");
}
__device__ __forceinline__ float gelu_tanh(float x) {
    float x3 = x * x * x;
    return 0.5f * x * (1.0f + tanhf(0.7978845608028654f * (x + 0.044715f * x3)));
}

// --------------------- branch s2: weight converts + zero --------------------
#define W4_COUNT   (NEXP * DM * MLPD / 4)
#define OUT4_COUNT (NTOK * DM / 4)

__global__ void convw1_kernel(const float* __restrict__ w1) {
    long long stride = (long long)gridDim.x * blockDim.x;
    for (long long j = blockIdx.x * (long long)blockDim.x + threadIdx.x;
         j < W4_COUNT; j += stride) {
        float4 v = ((const float4*)w1)[j];
        __half2* d = (__half2*)g_w1h + j * 2;
        d[0] = __floats2half2_rn(v.x, v.y);
        d[1] = __floats2half2_rn(v.z, v.w);
    }
}

__global__ void convw2z_kernel(const float* __restrict__ w2,
                               float* __restrict__ out) {
    long long stride = (long long)gridDim.x * blockDim.x;
    const long long total = W4_COUNT + OUT4_COUNT;
    for (long long i = blockIdx.x * (long long)blockDim.x + threadIdx.x;
         i < total; i += stride) {
        if (i < W4_COUNT) {
            float4 v = ((const float4*)w2)[i];
            __half2* d = (__half2*)g_w2h + i * 2;
            d[0] = __floats2half2_rn(v.x, v.y);
            d[1] = __floats2half2_rn(v.z, v.w);
        } else {
            ((float4*)out)[i - W4_COUNT] = make_float4(0.f, 0.f, 0.f, 0.f);
        }
    }
}

// -------------------- router weight transpose [D,E] -> [E,D] -----------------
__global__ void wrt_kernel(const float* __restrict__ wr0,
                           const float* __restrict__ wr1) {
    int i = blockIdx.x * blockDim.x + threadIdx.x;
    if (i >= DM * NEXP) return;
    int d = i / NEXP, e = i % NEXP;
    g_wrt[0][e * DM + d] = wr0[i];
    g_wrt[1][e * DM + d] = wr1[i];
}

// --------------------------- router (merged, smem weights) -------------------
// Also initializes g_row_src (16 ints per block; 1152 blocks * 16 = MTOT).
__global__ __launch_bounds__(256)
void router_kernel(const float* __restrict__ xdet,
                   const float* __restrict__ xcls) {
    __shared__ float sw[NEXP * DM];
    int b = blockIdx.x;
    int tid = threadIdx.x;
    if (tid < 16) g_row_src[b * 16 + tid] = -1;
    int which = (b < NTOK_DET / 8) ? 0 : 1;
    const float4* wsrc = (const float4*)g_wrt[which];
#pragma unroll
    for (int j = 0; j < 6; j++)
        ((float4*)sw)[j * 256 + tid] = wsrc[j * 256 + tid];
    __syncthreads();

    int wid = tid >> 5, lane = tid & 31;
    int t = b * 8 + wid;
    const float* xp = (t < NTOK_DET)
        ? (xdet + (size_t)t * DM)
        : (xcls + (size_t)(t - NTOK_DET) * DM);
    const float4* xr = (const float4*)xp;

    float acc[NEXP];
#pragma unroll
    for (int e = 0; e < NEXP; e++) acc[e] = 0.f;
#pragma unroll
    for (int it = 0; it < 6; it++) {
        int d4 = it * 32 + lane;
        float4 xv = xr[d4];
#pragma unroll
        for (int e = 0; e < NEXP; e++) {
            float4 wv = ((const float4*)(sw + e * DM))[d4];
            acc[e] += xv.x * wv.x + xv.y * wv.y + xv.z * wv.z + xv.w * wv.w;
        }
    }
#pragma unroll
    for (int e = 0; e < NEXP; e++) {
#pragma unroll
        for (int off = 16; off > 0; off >>= 1)
            acc[e] += __shfl_xor_sync(0xffffffffu, acc[e], off);
    }
    if (lane == 0) {
        float mx = acc[0];
#pragma unroll
        for (int e = 1; e < NEXP; e++) mx = fmaxf(mx, acc[e]);
        float p[NEXP]; float s = 0.f;
#pragma unroll
        for (int e = 0; e < NEXP; e++) { p[e] = expf(acc[e] - mx); s += p[e]; }
        float inv = 1.0f / s;
        int e0 = 0;
#pragma unroll
        for (int e = 1; e < NEXP; e++) if (p[e] > p[e0]) e0 = e;
        int e1 = (e0 == 0) ? 1 : 0;
#pragma unroll
        for (int e = 0; e < NEXP; e++) if (e != e0 && p[e] > p[e1]) e1 = e;
        g_tok_e[t][0] = (signed char)e0;
        g_tok_e[t][1] = (signed char)e1;
        g_tok_p[t][0] = p[e0] * inv;
        g_tok_p[t][1] = p[e1] * inv;
    }
}

// ------------------ positions (merged det+cls, grid 16) ----------------------
__global__ void positions_kernel() {
    __shared__ signed char se0[1024], se1[1024];
    __shared__ float sg0[1024], sg1[1024];
    int blk = blockIdx.x;
    int det = (blk < 8);
    int g = det ? blk : blk - 8;
    int S = det ? 1024 : 128;
    int C = det ? CAP_DET : CAP_CLS;
    int tok_base = det ? 0 : NTOK_DET;
    int row_off = det ? 0 : 2048;
    int tid = threadIdx.x;
    for (int t = tid; t < S; t += blockDim.x) {
        int gt = tok_base + g * S + t;
        se0[t] = g_tok_e[gt][0];
        se1[t] = g_tok_e[gt][1];
        sg0[t] = g_tok_p[gt][0];
        sg1[t] = g_tok_p[gt][1];
    }
    __syncthreads();
    int e = tid >> 5;
    int lane = tid & 31;
    int base = 0;
    int total = 2 * S;
    for (int j0 = 0; j0 < total; j0 += 32) {
        int j = j0 + lane;
        int exp_j = -1;
        if (j < total) exp_j = (j < S) ? (int)se0[j] : (int)se1[j - S];
        bool m = (exp_j == e);
        unsigned mask = __ballot_sync(0xffffffffu, m);
        if (m) {
            int pos = base + __popc(mask & ((1u << lane) - 1u));
            if (pos < C) {
                int t = (j < S) ? j : (j - S);
                int gt = tok_base + g * S + t;
                float gate = (j < S) ? sg0[t] : sg1[t];
                int row = e * RPE + row_off + g * C + pos;
                g_row_src[row] = gt;
                g_row_gate[row] = gate;
            }
        }
        base += __popc(mask);
    }
}

// --------------------------- gather (fp32 -> half) ---------------------------
__global__ void gather_kernel(const float* __restrict__ xdet,
                              const float* __restrict__ xcls) {
    int row = blockIdx.x;
    int i = threadIdx.x;
    int src = g_row_src[row];
    uint2 packed = make_uint2(0u, 0u);
    if (src >= 0) {
        const float* xp = (src < NTOK_DET)
            ? (xdet + (size_t)src * DM)
            : (xcls + (size_t)(src - NTOK_DET) * DM);
        float4 v = ((const float4*)xp)[i];
        __half2 h0 = __floats2half2_rn(v.x, v.y);
        __half2 h1 = __floats2half2_rn(v.z, v.w);
        packed.x = *(uint32_t*)&h0;
        packed.y = *(uint32_t*)&h1;
    }
    ((uint2*)(g_xg + (size_t)row * DM))[i] = packed;
}

// --------------------------- mma.sync fp16 GEMM ------------------------------
// FUSE=false: C[M,N] = gelu(A*W + b) stored half (GEMM1)
// FUSE=true : out[src(row)] += gate(row) * (A*W + b)   (GEMM2 + scatter)
template<int K, int NTOT, bool FUSE>
__device__ __forceinline__ void tc_gemm(const __half* __restrict__ A,
                                        const __half* __restrict__ W,
                                        const float* __restrict__ bias,
                                        __half* __restrict__ C,
                                        float* __restrict__ out) {
    extern __shared__ __half smem[];
    int tid = threadIdx.x;
    int wid = tid >> 5, lane = tid & 31;
    int gid = lane >> 2, tig = lane & 3;
    int warp_m = wid & 1, warp_n = wid >> 1;
    int m_base = warp_m * 64, n_base = warp_n * 32;
    int bx = blockIdx.x, by = blockIdx.y;
    int e = (by * 128) / RPE;
    const __half* Ab = A + (size_t)by * 128 * K;
    const __half* Wb = W + (size_t)e * K * NTOT + (size_t)bx * 128;

    uint32_t a_off = (uint32_t)((m_base + (lane & 15)) * ASTR + ((lane >> 4) << 3));
    uint32_t b_off = (uint32_t)((((lane >> 3) & 1) * 8 + (lane & 7)) * BSTR
                                + n_base + ((lane >> 4) << 3));

    float acc[4][4][4];
#pragma unroll
    for (int mi = 0; mi < 4; mi++)
#pragma unroll
        for (int ni = 0; ni < 4; ni++)
#pragma unroll
            for (int q = 0; q < 4; q++) acc[mi][ni][q] = 0.f;

    const int NC = K / CHUNK;
    uint32_t sbase = smem_u32(smem);

    auto issue_stage = [&](int c) {
        int buf = c % NBUF;
        uint32_t as = sbase + (uint32_t)(buf * STAGE_HALVES) * 2u;
        uint32_t bs = as + (uint32_t)A_HALVES * 2u;
        int kc = c * CHUNK;
#pragma unroll
        for (int j = 0; j < 4; j++) {
            int idx = j * 256 + tid;
            int row = idx >> 3, seg = idx & 7;
            cp_async16(as + (uint32_t)(row * ASTR + seg * 8) * 2u,
                       Ab + (size_t)row * K + kc + seg * 8);
        }
#pragma unroll
        for (int j = 0; j < 4; j++) {
            int idx = j * 256 + tid;
            int row = idx >> 4, seg = idx & 15;
            cp_async16(bs + (uint32_t)(row * BSTR + seg * 8) * 2u,
                       Wb + (size_t)(kc + row) * NTOT + seg * 8);
        }
        cp_commit();
    };

    issue_stage(0);
    if (NC > 1) issue_stage(1);
    for (int c = 0; c < NC; c++) {
        if (c + 1 < NC) cp_wait<1>(); else cp_wait<0>();
        __syncthreads();                       // publishes chunk c; fences c-1 reads
        if (c + 2 < NC) issue_stage(c + 2);    // safe: all warps done with this buf

        uint32_t as = sbase + (uint32_t)((c % NBUF) * STAGE_HALVES) * 2u;
        uint32_t bs = as + (uint32_t)A_HALVES * 2u;
        uint32_t a_base = as + a_off * 2u;
        uint32_t b_base = bs + b_off * 2u;
#pragma unroll
        for (int kk = 0; kk < CHUNK; kk += 16) {
            uint32_t afr[4][4];
#pragma unroll
            for (int mi = 0; mi < 4; mi++)
                ldsm_x4(afr[mi], a_base + (uint32_t)(mi * 16 * ASTR + kk) * 2u);
            uint32_t bfr[2][4];
#pragma unroll
            for (int p = 0; p < 2; p++)
                ldsm_x4_trans(bfr[p], b_base + (uint32_t)(kk * BSTR + p * 16) * 2u);
#pragma unroll
            for (int mi = 0; mi < 4; mi++)
#pragma unroll
                for (int ni = 0; ni < 4; ni++)
                    mma_f16(acc[mi][ni], afr[mi], &bfr[ni >> 1][(ni & 1) * 2]);
        }
    }

    if (!FUSE) {
#pragma unroll
        for (int ni = 0; ni < 4; ni++) {
            int cb = bx * 128 + n_base + ni * 8 + 2 * tig;
            float b0 = bias[e * NTOT + cb];
            float b1 = bias[e * NTOT + cb + 1];
#pragma unroll
            for (int mi = 0; mi < 4; mi++) {
                int r0 = by * 128 + m_base + mi * 16 + gid;
                float v0 = gelu_tanh(acc[mi][ni][0] + b0);
                float v1 = gelu_tanh(acc[mi][ni][1] + b1);
                float v2 = gelu_tanh(acc[mi][ni][2] + b0);
                float v3 = gelu_tanh(acc[mi][ni][3] + b1);
                *(__half2*)(C + (size_t)r0 * NTOT + cb)       = __floats2half2_rn(v0, v1);
                *(__half2*)(C + (size_t)(r0 + 8) * NTOT + cb) = __floats2half2_rn(v2, v3);
            }
        }
    } else {
        int rsrc[8]; float rg[8];
#pragma unroll
        for (int mi = 0; mi < 4; mi++) {
            int r0 = by * 128 + m_base + mi * 16 + gid;
            rsrc[mi * 2]     = __ldg(&g_row_src[r0]);
            rsrc[mi * 2 + 1] = __ldg(&g_row_src[r0 + 8]);
            rg[mi * 2]     = rsrc[mi * 2]     >= 0 ? __ldg(&g_row_gate[r0])     : 0.f;
            rg[mi * 2 + 1] = rsrc[mi * 2 + 1] >= 0 ? __ldg(&g_row_gate[r0 + 8]) : 0.f;
        }
#pragma unroll
        for (int ni = 0; ni < 4; ni++) {
            int cb = bx * 128 + n_base + ni * 8 + 2 * tig;
            float b0 = bias[e * NTOT + cb];
            float b1 = bias[e * NTOT + cb + 1];
#pragma unroll
            for (int mi = 0; mi < 4; mi++) {
                int src0 = rsrc[mi * 2], src1 = rsrc[mi * 2 + 1];
                if (src0 >= 0) {
                    float g0 = rg[mi * 2];
                    red_add_v2(out + (size_t)src0 * DM + cb,
                               g0 * (acc[mi][ni][0] + b0),
                               g0 * (acc[mi][ni][1] + b1));
                }
                if (src1 >= 0) {
                    float g1 = rg[mi * 2 + 1];
                    red_add_v2(out + (size_t)src1 * DM + cb,
                               g1 * (acc[mi][ni][2] + b0),
                               g1 * (acc[mi][ni][3] + b1));
                }
            }
        }
    }
}

__global__ __launch_bounds__(256, 2)
void gemm1_tc(const float* __restrict__ b1) {
    tc_gemm<DM, MLPD, false>(g_xg, g_w1h, b1, g_h, nullptr);
}
__global__ __launch_bounds__(256, 2)
void gemm2_tc(const float* __restrict__ b2, float* __restrict__ out) {
    tc_gemm<MLPD, DM, true>(g_h, g_w2h, b2, nullptr, out);
}

// --------------------------- launch -----------------------------------------
extern "C" void kernel_launch(void* const* d_in, const int* in_sizes, int n_in,
                              void* d_out, int out_size) {
    (void)in_sizes; (void)n_in; (void)out_size;
    const float* xdet = (const float*)d_in[0];
    const float* xcls = (const float*)d_in[1];
    const float* wrd  = (const float*)d_in[2];
    const float* wrc  = (const float*)d_in[3];
    const float* w1   = (const float*)d_in[4];
    const float* b1   = (const float*)d_in[5];
    const float* w2   = (const float*)d_in[6];
    const float* b2   = (const float*)d_in[7];
    float* out = (float*)d_out;

    static cudaStream_t s2 = nullptr;
    static cudaEvent_t ev0 = nullptr, ev1 = nullptr, ev2 = nullptr;
    if (!s2) {
        cudaStreamCreateWithFlags(&s2, cudaStreamNonBlocking);
        cudaEventCreateWithFlags(&ev0, cudaEventDisableTiming);
        cudaEventCreateWithFlags(&ev1, cudaEventDisableTiming);
        cudaEventCreateWithFlags(&ev2, cudaEventDisableTiming);
        cudaFuncSetAttribute(gemm1_tc, cudaFuncAttributeMaxDynamicSharedMemorySize, SMEM_DYN);
        cudaFuncSetAttribute(gemm2_tc, cudaFuncAttributeMaxDynamicSharedMemorySize, SMEM_DYN);
    }

    // fork: weight conversion branch on s2
    cudaEventRecord(ev0, 0);
    cudaStreamWaitEvent(s2, ev0, 0);
    convw1_kernel<<<2048, 256, 0, s2>>>(w1);
    cudaEventRecord(ev1, s2);
    convw2z_kernel<<<2048, 256, 0, s2>>>(w2, out);
    cudaEventRecord(ev2, s2);

    // main branch: routing pipeline
    wrt_kernel<<<(DM * NEXP + 255) / 256, 256>>>(wrd, wrc);
    router_kernel<<<NTOK / 8, 256>>>(xdet, xcls);
    positions_kernel<<<16, 256>>>();
    gather_kernel<<<MTOT, 192>>>(xdet, xcls);

    // join and run GEMMs
    cudaStreamWaitEvent(0, ev1, 0);
    gemm1_tc<<<dim3(MLPD / 128, MTOT / 128), 256, SMEM_DYN>>>(b1);
    cudaStreamWaitEvent(0, ev2, 0);
    gemm2_tc<<<dim3(DM / 128, MTOT / 128), 256, SMEM_DYN>>>(b2, out);
}

// round 17
// speedup vs baseline: 1.0853x; 1.0189x over previous
#include <cuda_runtime.h>
#include <cuda_fp16.h>
#include <math.h>
#include <stdint.h>

// ---------------------------------------------------------------------------
// MoE block via mma.sync fp16 (fp32 accum), ldmatrix(.trans), 3-stage
// cp.async pipeline (single-barrier mainloop), fused scatter epilogue with
// vectorized red.global.add.v2.f32, forked-stream prep overlap, MUFU-based
// tanh.approx GELU epilogue. tcgen05 unavailable (toolchain targets sm_103).
// ---------------------------------------------------------------------------

#define NEXP 8
#define DM 768
#define MLPD 3072
#define CAP_DET 256
#define CAP_CLS 32
#define RPE 2304
#define MTOT (NEXP * RPE)
#define NTOK_DET 8192
#define NTOK_CLS 1024
#define NTOK (NTOK_DET + NTOK_CLS)

#define CHUNK 64
#define ASTR 72
#define BSTR 136
#define A_HALVES (128 * ASTR)
#define B_HALVES (CHUNK * BSTR)
#define STAGE_HALVES (A_HALVES + B_HALVES)
#define NBUF 3
#define SMEM_DYN (NBUF * STAGE_HALVES * 2)   // 107520 bytes

// --------------------------- scratch ---------------------------------------
__device__ __half g_xg[(size_t)MTOT * DM];
__device__ __half g_h [(size_t)MTOT * MLPD];
__device__ __half g_w1h[(size_t)NEXP * DM * MLPD];   // [E, K=768,  N=3072]
__device__ __half g_w2h[(size_t)NEXP * MLPD * DM];   // [E, K=3072, N=768]
__device__ float  g_wrt[2][NEXP * DM];
__device__ int    g_row_src[MTOT];
__device__ float  g_row_gate[MTOT];
__device__ signed char g_tok_e[NTOK][2];
__device__ float  g_tok_p[NTOK][2];

// --------------------------- helpers ---------------------------------------
__device__ __forceinline__ uint32_t smem_u32(const void* p) {
    uint32_t a;
    asm("{ .reg .u64 t; cvta.to.shared.u64 t, %1; cvt.u32.u64 %0, t; }"
        : "=r"(a) : "l"(p));
    return a;
}
__device__ __forceinline__ void cp_async16(uint32_t sdst, const void* gsrc) {
    asm volatile("cp.async.cg.shared.global [%0], [%1], 16;"
                 :: "r"(sdst), "l"(gsrc) : "memory");
}
__device__ __forceinline__ void cp_commit() {
    asm volatile("cp.async.commit_group;" ::: "memory");
}
template<int N>
__device__ __forceinline__ void cp_wait() {
    asm volatile("cp.async.wait_group %0;" :: "n"(N) : "memory");
}
__device__ __forceinline__ void ldsm_x4(uint32_t* r, uint32_t addr) {
    asm volatile("ldmatrix.sync.aligned.m8n8.x4.shared.b16 {%0,%1,%2,%3}, [%4];"
                 : "=r"(r[0]), "=r"(r[1]), "=r"(r[2]), "=r"(r[3]) : "r"(addr));
}
__device__ __forceinline__ void ldsm_x4_trans(uint32_t* r, uint32_t addr) {
    asm volatile("ldmatrix.sync.aligned.m8n8.x4.trans.shared.b16 {%0,%1,%2,%3}, [%4];"
                 : "=r"(r[0]), "=r"(r[1]), "=r"(r[2]), "=r"(r[3]) : "r"(addr));
}
__device__ __forceinline__ void mma_f16(float* d, const uint32_t* a,
                                        const uint32_t* b) {
    asm volatile(
        "mma.sync.aligned.m16n8k16.row.col.f32.f16.f16.f32 "
        "{%0,%1,%2,%3}, {%4,%5,%6,%7}, {%8,%9}, {%0,%1,%2,%3};"
        : "+f"(d[0]), "+f"(d[1]), "+f"(d[2]), "+f"(d[3])
        : "r"(a[0]), "r"(a[1]), "r"(a[2]), "r"(a[3]),
          "r"(b[0]), "r"(b[1]));
}
// vectorized global reduction: out[0] += a, out[1] += b (8B-aligned addr)
__device__ __forceinline__ void red_add_v2(float* addr, float a, float b) {
    asm volatile("red.global.add.v2.f32 [%0], {%1, %2};"
                 :: "l"(addr), "f"(a), "f"(b) : "memory");
}
// HW tanh (MUFU.TANH, single instruction, max rel err ~2^-11 — same order as
// the fp16 rounding applied to h on store, so error adds in quadrature only)
__device__ __forceinline__ float tanh_hw(float x) {
    float r;
    asm("tanh.approx.f32 %0, %1;" : "=f"(r) : "f"(x));
    return r;
}
__device__ __forceinline__ float gelu_tanh(float x) {
    float x3 = x * x * x;
    return 0.5f * x * (1.0f + tanh_hw(0.7978845608028654f * (x + 0.044715f * x3)));
}

// --------------------- branch s2: weight converts + zero --------------------
#define W4_COUNT   (NEXP * DM * MLPD / 4)
#define OUT4_COUNT (NTOK * DM / 4)

__global__ void convw1_kernel(const float* __restrict__ w1) {
    long long stride = (long long)gridDim.x * blockDim.x;
    for (long long j = blockIdx.x * (long long)blockDim.x + threadIdx.x;
         j < W4_COUNT; j += stride) {
        float4 v = ((const float4*)w1)[j];
        __half2* d = (__half2*)g_w1h + j * 2;
        d[0] = __floats2half2_rn(v.x, v.y);
        d[1] = __floats2half2_rn(v.z, v.w);
    }
}

__global__ void convw2z_kernel(const float* __restrict__ w2,
                               float* __restrict__ out) {
    long long stride = (long long)gridDim.x * blockDim.x;
    const long long total = W4_COUNT + OUT4_COUNT;
    for (long long i = blockIdx.x * (long long)blockDim.x + threadIdx.x;
         i < total; i += stride) {
        if (i < W4_COUNT) {
            float4 v = ((const float4*)w2)[i];
            __half2* d = (__half2*)g_w2h + i * 2;
            d[0] = __floats2half2_rn(v.x, v.y);
            d[1] = __floats2half2_rn(v.z, v.w);
        } else {
            ((float4*)out)[i - W4_COUNT] = make_float4(0.f, 0.f, 0.f, 0.f);
        }
    }
}

// -------------------- router weight transpose [D,E] -> [E,D] -----------------
__global__ void wrt_kernel(const float* __restrict__ wr0,
                           const float* __restrict__ wr1) {
    int i = blockIdx.x * blockDim.x + threadIdx.x;
    if (i >= DM * NEXP) return;
    int d = i / NEXP, e = i % NEXP;
    g_wrt[0][e * DM + d] = wr0[i];
    g_wrt[1][e * DM + d] = wr1[i];
}

// --------------------------- router (merged, smem weights) -------------------
// Also initializes g_row_src (16 ints per block; 1152 blocks * 16 = MTOT).
__global__ __launch_bounds__(256)
void router_kernel(const float* __restrict__ xdet,
                   const float* __restrict__ xcls) {
    __shared__ float sw[NEXP * DM];
    int b = blockIdx.x;
    int tid = threadIdx.x;
    if (tid < 16) g_row_src[b * 16 + tid] = -1;
    int which = (b < NTOK_DET / 8) ? 0 : 1;
    const float4* wsrc = (const float4*)g_wrt[which];
#pragma unroll
    for (int j = 0; j < 6; j++)
        ((float4*)sw)[j * 256 + tid] = wsrc[j * 256 + tid];
    __syncthreads();

    int wid = tid >> 5, lane = tid & 31;
    int t = b * 8 + wid;
    const float* xp = (t < NTOK_DET)
        ? (xdet + (size_t)t * DM)
        : (xcls + (size_t)(t - NTOK_DET) * DM);
    const float4* xr = (const float4*)xp;

    float acc[NEXP];
#pragma unroll
    for (int e = 0; e < NEXP; e++) acc[e] = 0.f;
#pragma unroll
    for (int it = 0; it < 6; it++) {
        int d4 = it * 32 + lane;
        float4 xv = xr[d4];
#pragma unroll
        for (int e = 0; e < NEXP; e++) {
            float4 wv = ((const float4*)(sw + e * DM))[d4];
            acc[e] += xv.x * wv.x + xv.y * wv.y + xv.z * wv.z + xv.w * wv.w;
        }
    }
#pragma unroll
    for (int e = 0; e < NEXP; e++) {
#pragma unroll
        for (int off = 16; off > 0; off >>= 1)
            acc[e] += __shfl_xor_sync(0xffffffffu, acc[e], off);
    }
    if (lane == 0) {
        float mx = acc[0];
#pragma unroll
        for (int e = 1; e < NEXP; e++) mx = fmaxf(mx, acc[e]);
        float p[NEXP]; float s = 0.f;
#pragma unroll
        for (int e = 0; e < NEXP; e++) { p[e] = expf(acc[e] - mx); s += p[e]; }
        float inv = 1.0f / s;
        int e0 = 0;
#pragma unroll
        for (int e = 1; e < NEXP; e++) if (p[e] > p[e0]) e0 = e;
        int e1 = (e0 == 0) ? 1 : 0;
#pragma unroll
        for (int e = 0; e < NEXP; e++) if (e != e0 && p[e] > p[e1]) e1 = e;
        g_tok_e[t][0] = (signed char)e0;
        g_tok_e[t][1] = (signed char)e1;
        g_tok_p[t][0] = p[e0] * inv;
        g_tok_p[t][1] = p[e1] * inv;
    }
}

// ------------------ positions (merged det+cls, grid 16) ----------------------
__global__ void positions_kernel() {
    __shared__ signed char se0[1024], se1[1024];
    __shared__ float sg0[1024], sg1[1024];
    int blk = blockIdx.x;
    int det = (blk < 8);
    int g = det ? blk : blk - 8;
    int S = det ? 1024 : 128;
    int C = det ? CAP_DET : CAP_CLS;
    int tok_base = det ? 0 : NTOK_DET;
    int row_off = det ? 0 : 2048;
    int tid = threadIdx.x;
    for (int t = tid; t < S; t += blockDim.x) {
        int gt = tok_base + g * S + t;
        se0[t] = g_tok_e[gt][0];
        se1[t] = g_tok_e[gt][1];
        sg0[t] = g_tok_p[gt][0];
        sg1[t] = g_tok_p[gt][1];
    }
    __syncthreads();
    int e = tid >> 5;
    int lane = tid & 31;
    int base = 0;
    int total = 2 * S;
    for (int j0 = 0; j0 < total; j0 += 32) {
        int j = j0 + lane;
        int exp_j = -1;
        if (j < total) exp_j = (j < S) ? (int)se0[j] : (int)se1[j - S];
        bool m = (exp_j == e);
        unsigned mask = __ballot_sync(0xffffffffu, m);
        if (m) {
            int pos = base + __popc(mask & ((1u << lane) - 1u));
            if (pos < C) {
                int t = (j < S) ? j : (j - S);
                int gt = tok_base + g * S + t;
                float gate = (j < S) ? sg0[t] : sg1[t];
                int row = e * RPE + row_off + g * C + pos;
                g_row_src[row] = gt;
                g_row_gate[row] = gate;
            }
        }
        base += __popc(mask);
    }
}

// --------------------------- gather (fp32 -> half) ---------------------------
__global__ void gather_kernel(const float* __restrict__ xdet,
                              const float* __restrict__ xcls) {
    int row = blockIdx.x;
    int i = threadIdx.x;
    int src = g_row_src[row];
    uint2 packed = make_uint2(0u, 0u);
    if (src >= 0) {
        const float* xp = (src < NTOK_DET)
            ? (xdet + (size_t)src * DM)
            : (xcls + (size_t)(src - NTOK_DET) * DM);
        float4 v = ((const float4*)xp)[i];
        __half2 h0 = __floats2half2_rn(v.x, v.y);
        __half2 h1 = __floats2half2_rn(v.z, v.w);
        packed.x = *(uint32_t*)&h0;
        packed.y = *(uint32_t*)&h1;
    }
    ((uint2*)(g_xg + (size_t)row * DM))[i] = packed;
}

// --------------------------- mma.sync fp16 GEMM ------------------------------
// FUSE=false: C[M,N] = gelu(A*W + b) stored half (GEMM1)
// FUSE=true : out[src(row)] += gate(row) * (A*W + b)   (GEMM2 + scatter)
template<int K, int NTOT, bool FUSE>
__device__ __forceinline__ void tc_gemm(const __half* __restrict__ A,
                                        const __half* __restrict__ W,
                                        const float* __restrict__ bias,
                                        __half* __restrict__ C,
                                        float* __restrict__ out) {
    extern __shared__ __half smem[];
    int tid = threadIdx.x;
    int wid = tid >> 5, lane = tid & 31;
    int gid = lane >> 2, tig = lane & 3;
    int warp_m = wid & 1, warp_n = wid >> 1;
    int m_base = warp_m * 64, n_base = warp_n * 32;
    int bx = blockIdx.x, by = blockIdx.y;
    int e = (by * 128) / RPE;
    const __half* Ab = A + (size_t)by * 128 * K;
    const __half* Wb = W + (size_t)e * K * NTOT + (size_t)bx * 128;

    uint32_t a_off = (uint32_t)((m_base + (lane & 15)) * ASTR + ((lane >> 4) << 3));
    uint32_t b_off = (uint32_t)((((lane >> 3) & 1) * 8 + (lane & 7)) * BSTR
                                + n_base + ((lane >> 4) << 3));

    float acc[4][4][4];
#pragma unroll
    for (int mi = 0; mi < 4; mi++)
#pragma unroll
        for (int ni = 0; ni < 4; ni++)
#pragma unroll
            for (int q = 0; q < 4; q++) acc[mi][ni][q] = 0.f;

    const int NC = K / CHUNK;
    uint32_t sbase = smem_u32(smem);

    auto issue_stage = [&](int c) {
        int buf = c % NBUF;
        uint32_t as = sbase + (uint32_t)(buf * STAGE_HALVES) * 2u;
        uint32_t bs = as + (uint32_t)A_HALVES * 2u;
        int kc = c * CHUNK;
#pragma unroll
        for (int j = 0; j < 4; j++) {
            int idx = j * 256 + tid;
            int row = idx >> 3, seg = idx & 7;
            cp_async16(as + (uint32_t)(row * ASTR + seg * 8) * 2u,
                       Ab + (size_t)row * K + kc + seg * 8);
        }
#pragma unroll
        for (int j = 0; j < 4; j++) {
            int idx = j * 256 + tid;
            int row = idx >> 4, seg = idx & 15;
            cp_async16(bs + (uint32_t)(row * BSTR + seg * 8) * 2u,
                       Wb + (size_t)(kc + row) * NTOT + seg * 8);
        }
        cp_commit();
    };

    issue_stage(0);
    if (NC > 1) issue_stage(1);
    for (int c = 0; c < NC; c++) {
        if (c + 1 < NC) cp_wait<1>(); else cp_wait<0>();
        __syncthreads();                       // publishes chunk c; fences c-1 reads
        if (c + 2 < NC) issue_stage(c + 2);    // safe: all warps done with this buf

        uint32_t as = sbase + (uint32_t)((c % NBUF) * STAGE_HALVES) * 2u;
        uint32_t bs = as + (uint32_t)A_HALVES * 2u;
        uint32_t a_base = as + a_off * 2u;
        uint32_t b_base = bs + b_off * 2u;
#pragma unroll
        for (int kk = 0; kk < CHUNK; kk += 16) {
            uint32_t afr[4][4];
#pragma unroll
            for (int mi = 0; mi < 4; mi++)
                ldsm_x4(afr[mi], a_base + (uint32_t)(mi * 16 * ASTR + kk) * 2u);
            uint32_t bfr[2][4];
#pragma unroll
            for (int p = 0; p < 2; p++)
                ldsm_x4_trans(bfr[p], b_base + (uint32_t)(kk * BSTR + p * 16) * 2u);
#pragma unroll
            for (int mi = 0; mi < 4; mi++)
#pragma unroll
                for (int ni = 0; ni < 4; ni++)
                    mma_f16(acc[mi][ni], afr[mi], &bfr[ni >> 1][(ni & 1) * 2]);
        }
    }

    if (!FUSE) {
#pragma unroll
        for (int ni = 0; ni < 4; ni++) {
            int cb = bx * 128 + n_base + ni * 8 + 2 * tig;
            float b0 = bias[e * NTOT + cb];
            float b1 = bias[e * NTOT + cb + 1];
#pragma unroll
            for (int mi = 0; mi < 4; mi++) {
                int r0 = by * 128 + m_base + mi * 16 + gid;
                float v0 = gelu_tanh(acc[mi][ni][0] + b0);
                float v1 = gelu_tanh(acc[mi][ni][1] + b1);
                float v2 = gelu_tanh(acc[mi][ni][2] + b0);
                float v3 = gelu_tanh(acc[mi][ni][3] + b1);
                *(__half2*)(C + (size_t)r0 * NTOT + cb)       = __floats2half2_rn(v0, v1);
                *(__half2*)(C + (size_t)(r0 + 8) * NTOT + cb) = __floats2half2_rn(v2, v3);
            }
        }
    } else {
        int rsrc[8]; float rg[8];
#pragma unroll
        for (int mi = 0; mi < 4; mi++) {
            int r0 = by * 128 + m_base + mi * 16 + gid;
            rsrc[mi * 2]     = __ldg(&g_row_src[r0]);
            rsrc[mi * 2 + 1] = __ldg(&g_row_src[r0 + 8]);
            rg[mi * 2]     = rsrc[mi * 2]     >= 0 ? __ldg(&g_row_gate[r0])     : 0.f;
            rg[mi * 2 + 1] = rsrc[mi * 2 + 1] >= 0 ? __ldg(&g_row_gate[r0 + 8]) : 0.f;
        }
#pragma unroll
        for (int ni = 0; ni < 4; ni++) {
            int cb = bx * 128 + n_base + ni * 8 + 2 * tig;
            float b0 = bias[e * NTOT + cb];
            float b1 = bias[e * NTOT + cb + 1];
#pragma unroll
            for (int mi = 0; mi < 4; mi++) {
                int src0 = rsrc[mi * 2], src1 = rsrc[mi * 2 + 1];
                if (src0 >= 0) {
                    float g0 = rg[mi * 2];
                    red_add_v2(out + (size_t)src0 * DM + cb,
                               g0 * (acc[mi][ni][0] + b0),
                               g0 * (acc[mi][ni][1] + b1));
                }
                if (src1 >= 0) {
                    float g1 = rg[mi * 2 + 1];
                    red_add_v2(out + (size_t)src1 * DM + cb,
                               g1 * (acc[mi][ni][2] + b0),
                               g1 * (acc[mi][ni][3] + b1));
                }
            }
        }
    }
}

__global__ __launch_bounds__(256, 2)
void gemm1_tc(const float* __restrict__ b1) {
    tc_gemm<DM, MLPD, false>(g_xg, g_w1h, b1, g_h, nullptr);
}
__global__ __launch_bounds__(256, 2)
void gemm2_tc(const float* __restrict__ b2, float* __restrict__ out) {
    tc_gemm<MLPD, DM, true>(g_h, g_w2h, b2, nullptr, out);
}

// --------------------------- launch -----------------------------------------
extern "C" void kernel_launch(void* const* d_in, const int* in_sizes, int n_in,
                              void* d_out, int out_size) {
    (void)in_sizes; (void)n_in; (void)out_size;
    const float* xdet = (const float*)d_in[0];
    const float* xcls = (const float*)d_in[1];
    const float* wrd  = (const float*)d_in[2];
    const float* wrc  = (const float*)d_in[3];
    const float* w1   = (const float*)d_in[4];
    const float* b1   = (const float*)d_in[5];
    const float* w2   = (const float*)d_in[6];
    const float* b2   = (const float*)d_in[7];
    float* out = (float*)d_out;

    static cudaStream_t s2 = nullptr;
    static cudaEvent_t ev0 = nullptr, ev1 = nullptr, ev2 = nullptr;
    if (!s2) {
        cudaStreamCreateWithFlags(&s2, cudaStreamNonBlocking);
        cudaEventCreateWithFlags(&ev0, cudaEventDisableTiming);
        cudaEventCreateWithFlags(&ev1, cudaEventDisableTiming);
        cudaEventCreateWithFlags(&ev2, cudaEventDisableTiming);
        cudaFuncSetAttribute(gemm1_tc, cudaFuncAttributeMaxDynamicSharedMemorySize, SMEM_DYN);
        cudaFuncSetAttribute(gemm2_tc, cudaFuncAttributeMaxDynamicSharedMemorySize, SMEM_DYN);
    }

    // fork: weight conversion branch on s2
    cudaEventRecord(ev0, 0);
    cudaStreamWaitEvent(s2, ev0, 0);
    convw1_kernel<<<2048, 256, 0, s2>>>(w1);
    cudaEventRecord(ev1, s2);
    convw2z_kernel<<<2048, 256, 0, s2>>>(w2, out);
    cudaEventRecord(ev2, s2);

    // main branch: routing pipeline
    wrt_kernel<<<(DM * NEXP + 255) / 256, 256>>>(wrd, wrc);
    router_kernel<<<NTOK / 8, 256>>>(xdet, xcls);
    positions_kernel<<<16, 256>>>();
    gather_kernel<<<MTOT, 192>>>(xdet, xcls);

    // join and run GEMMs
    cudaStreamWaitEvent(0, ev1, 0);
    gemm1_tc<<<dim3(MLPD / 128, MTOT / 128), 256, SMEM_DYN>>>(b1);
    cudaStreamWaitEvent(0, ev2, 0);
    gemm2_tc<<<dim3(DM / 128, MTOT / 128), 256, SMEM_DYN>>>(b2, out);
}